// round 15
// baseline (speedup 1.0000x reference)
#include <cuda_runtime.h>

#define BATCH 256

// ---------------- device scratch (no allocations allowed) ----------------
__device__ float g_W1[8  * 3  * 7 * 12];            // folded weights [o][c][g][12]
__device__ float g_W2[16 * 8  * 7 * 12];
__device__ float g_W3[32 * 16 * 7 * 12];
__device__ float g_E2[BATCH * 8  * 18 * 7 * 18];    // [b][c][y][g][x], padded 18x18
__device__ float g_E3[BATCH * 16 * 10 * 7 * 10];    // [b][c][y][g][x], padded 10x10
__device__ float g_out3[BATCH * 32 * 4 * 4];

// ---------------- spline/silu feature expansion ----------------
__device__ __forceinline__ void compute_phi(float v, float* phi) {
    const float h = 2.0f / 3.0f;
    float b[9];
#pragma unroll
    for (int i = 0; i < 9; i++) {
        float t0 = (i - 3) * h - 1.0f;
        float t1 = (i - 2) * h - 1.0f;
        b[i] = (v >= t0 && v < t1) ? 1.0f : 0.0f;
    }
#pragma unroll
    for (int j = 1; j <= 3; j++) {
        float inv = 1.0f / (j * h);
#pragma unroll
        for (int i = 0; i + j < 9; i++) {
            float ti  = (i - 3) * h - 1.0f;
            float tj1 = (i + j - 2) * h - 1.0f;
            b[i] = (v - ti) * inv * b[i] + (tj1 - v) * inv * b[i + 1];
        }
    }
    phi[0] = v / (1.0f + __expf(-v));
#pragma unroll
    for (int g = 0; g < 6; g++) phi[g + 1] = b[g];
}

// ---------------- prep: fold scaler into [o][c][g][12] ----------------
template <int O, int C>
__device__ __forceinline__ void fold_w(float* Wd, int i, const float* __restrict__ bw,
                                       const float* __restrict__ sw, const float* __restrict__ sc) {
    int kp = i % 12;
    int g  = (i / 12) % 7;
    int c  = (i / 84) % C;
    int o  = i / (84 * C);
    float val = 0.0f;
    if (kp < 9) {
        int f = c * 9 + kp;
        constexpr int F = C * 9;
        val = (g == 0) ? bw[o * F + f] : sw[(o * F + f) * 6 + (g - 1)] * sc[o * F + f];
    }
    Wd[i] = val;
}

#define NPREP (2016 + 10752 + 43008)

__global__ void prep_all(
    const float* __restrict__ c1bw, const float* __restrict__ c1sw, const float* __restrict__ c1sc,
    const float* __restrict__ c2bw, const float* __restrict__ c2sw, const float* __restrict__ c2sc,
    const float* __restrict__ c3bw, const float* __restrict__ c3sw, const float* __restrict__ c3sc)
{
    int i = blockIdx.x * blockDim.x + threadIdx.x;
    if (i < 2016) {
        fold_w<8, 3>(g_W1, i, c1bw, c1sw, c1sc);
    } else if (i < 2016 + 10752) {
        fold_w<16, 8>(g_W2, i - 2016, c2bw, c2sw, c2sc);
    } else if (i < NPREP) {
        fold_w<32, 16>(g_W3, i - 12768, c3bw, c3sw, c3sc);
    }
}

// ---------------- init: fill E2/E3 with phi(0) (borders survive; interior overwritten) ----
__global__ void __launch_bounds__(256) init23_k() {
    const int b = blockIdx.x, tid = threadIdx.x;
    float phi0[7];
    compute_phi(0.0f, phi0);
    for (int i = tid; i < 8 * 18 * 18; i += 256) {
        int c = i / 324, r = i % 324, y = r / 18, x = r % 18;
        float* p = &g_E2[((size_t)(b * 8 + c) * 18 + y) * 126 + x];
#pragma unroll
        for (int g = 0; g < 7; g++) p[g * 18] = phi0[g];
    }
    for (int i = tid; i < 16 * 10 * 10; i += 256) {
        int c = i / 100, r = i % 100, y = r / 10, x = r % 10;
        float* p = &g_E3[((size_t)(b * 16 + c) * 10 + y) * 70 + x];
#pragma unroll
        for (int g = 0; g < 7; g++) p[g * 10] = phi0[g];
    }
}

// ---------------- FFMA micro-kernel on a 4x4 e-patch, OT output channels ----------------
template <int OT, int C_total>
__device__ __forceinline__ void fma_patch(
    const float e[4][4], const float* __restrict__ Wg, float acc[OT][4], int og_base, int c, int g)
{
#pragma unroll
    for (int o = 0; o < OT; o++) {
        const float4* wv = reinterpret_cast<const float4*>(
            &Wg[(((og_base + o * C_total) + c) * 7 + g) * 12]);
        float4 w0 = __ldg(&wv[0]);
        float4 w1 = __ldg(&wv[1]);
        float4 w2 = __ldg(&wv[2]);
        float wk[9] = {w0.x, w0.y, w0.z, w0.w, w1.x, w1.y, w1.z, w1.w, w2.x};
#pragma unroll
        for (int kh = 0; kh < 3; kh++)
#pragma unroll
            for (int kw = 0; kw < 3; kw++) {
                float wgt = wk[kh * 3 + kw];
                acc[o][0] += e[kh][kw] * wgt;
                acc[o][1] += e[kh][kw + 1] * wgt;
                acc[o][2] += e[kh + 1][kw] * wgt;
                acc[o][3] += e[kh + 1][kw + 1] * wgt;
            }
    }
}

// ---------------- layer 1: smem expansion + conv + pool + phi-epilogue -> g_E2 ----------------
__global__ void __launch_bounds__(64, 8) conv1_k(const float* __restrict__ x) {
    // C=3 H=W=32 O=8 OT=4 OG=2 SR=2; 8 strips/img, grid 2048, smem E[3][6][7][34]
    extern __shared__ float E[];
    const int b   = blockIdx.x / 8;
    const int s   = blockIdx.x % 8;
    const int tid = threadIdx.x;

    const float* inb = x + (size_t)b * 3072;
    const int gy0 = 4 * s - 1;
    for (int i = tid; i < 3 * 6 * 34; i += 64) {
        int xx = i % 34;
        int ly = (i / 34) % 6;
        int c  = i / 204;
        int gy = gy0 + ly;
        float v = 0.0f;
        if (gy >= 0 && gy < 32 && xx >= 1 && xx <= 32) v = __ldg(&inb[(c * 32 + gy) * 32 + xx - 1]);
        float ph[7];
        compute_phi(v, ph);
#pragma unroll
        for (int g = 0; g < 7; g++) E[((c * 6 + ly) * 7 + g) * 34 + xx] = ph[g];
    }
    __syncthreads();

    const int px = tid % 16;
    const int pr = (tid / 16) % 2;
    const int og = tid / 32;

    float acc[4][4];
#pragma unroll
    for (int o = 0; o < 4; o++) acc[o][0] = acc[o][1] = acc[o][2] = acc[o][3] = 0.0f;

#pragma unroll 1
    for (int c = 0; c < 3; c++) {
#pragma unroll
        for (int g = 0; g < 7; g++) {
            float e[4][4];
            const int base = ((c * 6 + 2 * pr) * 7 + g) * 34 + 2 * px;
#pragma unroll
            for (int dy = 0; dy < 4; dy++) {
                const float2* r = reinterpret_cast<const float2*>(&E[base + dy * 7 * 34]);
                float2 a = r[0], b2 = r[1];
                e[dy][0] = a.x; e[dy][1] = a.y; e[dy][2] = b2.x; e[dy][3] = b2.y;
            }
            fma_patch<4, 3>(e, g_W1, acc, og * 4 * 3, c, g);
        }
    }

    const int prow = s * 2 + pr;
#pragma unroll
    for (int o = 0; o < 4; o++) {
        float m = fmaxf(fmaxf(acc[o][0], acc[o][1]), fmaxf(acc[o][2], acc[o][3]));
        float ph[7];
        compute_phi(m, ph);
        float* p = &g_E2[((size_t)(b * 8 + og * 4 + o) * 18 + (prow + 1)) * 126 + (px + 1)];
#pragma unroll
        for (int g = 0; g < 7; g++) p[g * 18] = ph[g];
    }
}

// ---------------- layer 2: streaming conv from g_E2, phi-epilogue -> g_E3 ----------------
__global__ void __launch_bounds__(64, 8) conv2_k() {
    // C=8 H=W=16 O=16 OT=4 OG=4 SR=2; 4 strips/img, grid 1024, no smem
    const int b   = blockIdx.x / 4;
    const int s   = blockIdx.x % 4;
    const int tid = threadIdx.x;
    const int px  = tid % 8;
    const int pr  = (tid / 8) % 2;
    const int og  = tid / 16;
    const int prow = s * 2 + pr;
    const int y0   = 2 * prow;

    const float* Eb = g_E2 + (size_t)b * 8 * 18 * 126;

    float acc[4][4];
#pragma unroll
    for (int o = 0; o < 4; o++) acc[o][0] = acc[o][1] = acc[o][2] = acc[o][3] = 0.0f;

#pragma unroll 1
    for (int c = 0; c < 8; c++) {
#pragma unroll
        for (int g = 0; g < 7; g++) {
            float e[4][4];
            const float* base = Eb + (c * 18 + y0) * 126 + g * 18 + 2 * px;
#pragma unroll
            for (int dy = 0; dy < 4; dy++) {
                const float2* r = reinterpret_cast<const float2*>(base + dy * 126);
                float2 a = __ldg(r), b2 = __ldg(r + 1);
                e[dy][0] = a.x; e[dy][1] = a.y; e[dy][2] = b2.x; e[dy][3] = b2.y;
            }
            fma_patch<4, 8>(e, g_W2, acc, og * 4 * 8, c, g);
        }
    }

#pragma unroll
    for (int o = 0; o < 4; o++) {
        float m = fmaxf(fmaxf(acc[o][0], acc[o][1]), fmaxf(acc[o][2], acc[o][3]));
        float ph[7];
        compute_phi(m, ph);
        float* p = &g_E3[((size_t)(b * 16 + og * 4 + o) * 10 + (prow + 1)) * 70 + (px + 1)];
#pragma unroll
        for (int g = 0; g < 7; g++) p[g * 10] = ph[g];
    }
}

// ---------------- layer 3: streaming conv from g_E3, CS=2 combine -> g_out3 ----------------
__global__ void __launch_bounds__(128, 4) conv3_k() {
    // C=16 H=W=8 O=32 OT=4 OG=8 SR=2 CS=2; 2 strips/img, grid 512
    __shared__ float P[64 * 17];
    const int b   = blockIdx.x / 2;
    const int s   = blockIdx.x % 2;
    const int tid = threadIdx.x;
    const int px  = tid % 4;
    const int pr  = (tid / 4) % 2;
    const int og  = (tid / 8) % 8;
    const int cs  = tid / 64;
    const int prow = s * 2 + pr;
    const int y0   = 2 * prow;

    const float* Eb = g_E3 + (size_t)b * 16 * 10 * 70;

    float acc[4][4];
#pragma unroll
    for (int o = 0; o < 4; o++) acc[o][0] = acc[o][1] = acc[o][2] = acc[o][3] = 0.0f;

#pragma unroll 1
    for (int cc = 0; cc < 8; cc++) {
        int c = cs * 8 + cc;
#pragma unroll
        for (int g = 0; g < 7; g++) {
            float e[4][4];
            const float* base = Eb + (c * 10 + y0) * 70 + g * 10 + 2 * px;
#pragma unroll
            for (int dy = 0; dy < 4; dy++) {
                const float2* r = reinterpret_cast<const float2*>(base + dy * 70);
                float2 a = __ldg(r), b2 = __ldg(r + 1);
                e[dy][0] = a.x; e[dy][1] = a.y; e[dy][2] = b2.x; e[dy][3] = b2.y;
            }
            fma_patch<4, 16>(e, g_W3, acc, og * 4 * 16, c, g);
        }
    }

    const int slot = tid % 64;
    if (cs == 1) {
#pragma unroll
        for (int o = 0; o < 4; o++)
#pragma unroll
            for (int k = 0; k < 4; k++) P[slot * 17 + o * 4 + k] = acc[o][k];
    }
    __syncthreads();
    if (cs == 0) {
#pragma unroll
        for (int o = 0; o < 4; o++) {
            float v0 = acc[o][0] + P[slot * 17 + o * 4 + 0];
            float v1 = acc[o][1] + P[slot * 17 + o * 4 + 1];
            float v2 = acc[o][2] + P[slot * 17 + o * 4 + 2];
            float v3 = acc[o][3] + P[slot * 17 + o * 4 + 3];
            float m = fmaxf(fmaxf(v0, v1), fmaxf(v2, v3));
            g_out3[((size_t)(b * 32 + og * 4 + o) * 4 + prow) * 4 + px] = m;
        }
    }
}

// ---------------- final linear 512 -> 100 (direct linw rows, float4) ----------------
__global__ void __launch_bounds__(128) linear_k(const float* __restrict__ linw,
                                                const float* __restrict__ bias,
                                                float* __restrict__ out) {
    __shared__ float hs[512];
    int b = blockIdx.x;
    for (int i = threadIdx.x; i < 512; i += 128) hs[i] = g_out3[(size_t)b * 512 + i];
    __syncthreads();
    int j = threadIdx.x;
    if (j < 100) {
        float a = __ldg(&bias[j]);
        const float4* wr = reinterpret_cast<const float4*>(linw + (size_t)j * 512);
        const float4* h4 = reinterpret_cast<const float4*>(hs);
#pragma unroll 8
        for (int f = 0; f < 128; f++) {
            float4 w = __ldg(&wr[f]);
            float4 hv = h4[f];
            a += w.x * hv.x + w.y * hv.y + w.z * hv.z + w.w * hv.w;
        }
        out[(size_t)b * 100 + j] = a;
    }
}

// ---------------- launch ----------------
extern "C" void kernel_launch(void* const* d_in, const int* in_sizes, int n_in,
                              void* d_out, int out_size) {
    const float* x     = (const float*)d_in[0];
    const float* c1bw  = (const float*)d_in[1];
    const float* c1sw  = (const float*)d_in[2];
    const float* c1sc  = (const float*)d_in[3];
    const float* c2bw  = (const float*)d_in[4];
    const float* c2sw  = (const float*)d_in[5];
    const float* c2sc  = (const float*)d_in[6];
    const float* c3bw  = (const float*)d_in[7];
    const float* c3sw  = (const float*)d_in[8];
    const float* c3sc  = (const float*)d_in[9];
    const float* linw  = (const float*)d_in[10];
    const float* linb  = (const float*)d_in[11];
    float* out = (float*)d_out;

    static cudaStream_t s1;
    static cudaEvent_t ev_fork, ev_join;
    static bool init = false;
    if (!init) {
        cudaStreamCreateWithFlags(&s1, cudaStreamNonBlocking);
        cudaEventCreateWithFlags(&ev_fork, cudaEventDisableTiming);
        cudaEventCreateWithFlags(&ev_join, cudaEventDisableTiming);
        init = true;
    }

    // prep (weights) on main stream; E2/E3 phi(0) fill concurrently on s1
    cudaEventRecord(ev_fork, 0);
    cudaStreamWaitEvent(s1, ev_fork, 0);
    init23_k<<<BATCH, 256, 0, s1>>>();
    prep_all<<<(NPREP + 255) / 256, 256>>>(c1bw, c1sw, c1sc, c2bw, c2sw, c2sc,
                                           c3bw, c3sw, c3sc);
    cudaEventRecord(ev_join, s1);
    cudaStreamWaitEvent(0, ev_join, 0);

    conv1_k<<<BATCH * 8, 64, 3 * 6 * 7 * 34 * 4>>>(x);   // 17136 B smem
    conv2_k<<<BATCH * 4, 64>>>();
    conv3_k<<<BATCH * 2, 128>>>();
    linear_k<<<BATCH, 128>>>(linw, linb, out);
}

// round 17
// speedup vs baseline: 1.0398x; 1.0398x over previous
#include <cuda_runtime.h>

#define BATCH 256

// ---------------- device scratch (no allocations allowed) ----------------
__device__ float g_W1[8  * 3  * 7 * 12];   // 2016
__device__ float g_W2[16 * 8  * 7 * 12];   // 10752
__device__ float g_W3[32 * 16 * 7 * 12];   // 43008
__device__ float g_out1[BATCH * 8  * 16 * 16];
__device__ float g_out2[BATCH * 16 * 8 * 8];
__device__ float g_out3[BATCH * 32 * 4 * 4];

// ---------------- spline/silu feature expansion ----------------
__device__ __forceinline__ void compute_phi(float v, float* phi) {
    const float h = 2.0f / 3.0f;
    float b[9];
#pragma unroll
    for (int i = 0; i < 9; i++) {
        float t0 = (i - 3) * h - 1.0f;
        float t1 = (i - 2) * h - 1.0f;
        b[i] = (v >= t0 && v < t1) ? 1.0f : 0.0f;
    }
#pragma unroll
    for (int j = 1; j <= 3; j++) {
        float inv = 1.0f / (j * h);
#pragma unroll
        for (int i = 0; i + j < 9; i++) {
            float ti  = (i - 3) * h - 1.0f;
            float tj1 = (i + j - 2) * h - 1.0f;
            b[i] = (v - ti) * inv * b[i] + (tj1 - v) * inv * b[i + 1];
        }
    }
    phi[0] = v / (1.0f + __expf(-v));
#pragma unroll
    for (int g = 0; g < 6; g++) phi[g + 1] = b[g];
}

// ---------------- prep: fold scaler into [o][c][g][12] ----------------
template <int O, int C>
__device__ __forceinline__ void fold_w(float* Wd, int i, const float* __restrict__ bw,
                                       const float* __restrict__ sw, const float* __restrict__ sc) {
    int kp = i % 12;
    int g  = (i / 12) % 7;
    int c  = (i / 84) % C;
    int o  = i / (84 * C);
    float val = 0.0f;
    if (kp < 9) {
        int f = c * 9 + kp;
        constexpr int F = C * 9;
        val = (g == 0) ? bw[o * F + f] : sw[(o * F + f) * 6 + (g - 1)] * sc[o * F + f];
    }
    Wd[i] = val;
}

#define NPREP (2016 + 10752 + 43008)

__global__ void prep_all(
    const float* __restrict__ c1bw, const float* __restrict__ c1sw, const float* __restrict__ c1sc,
    const float* __restrict__ c2bw, const float* __restrict__ c2sw, const float* __restrict__ c2sc,
    const float* __restrict__ c3bw, const float* __restrict__ c3sw, const float* __restrict__ c3sc)
{
    int i = blockIdx.x * blockDim.x + threadIdx.x;
    if (i < 2016) {
        fold_w<8, 3>(g_W1, i, c1bw, c1sw, c1sc);
    } else if (i < 2016 + 10752) {
        fold_w<16, 8>(g_W2, i - 2016, c2bw, c2sw, c2sc);
    } else if (i < NPREP) {
        fold_w<32, 16>(g_W3, i - 12768, c3bw, c3sw, c3sc);
    }
}

// ---------------- generic conv inner loop over CT channels ----------------
template <int CT, int OT, int Yd, int Xd>
__device__ __forceinline__ void conv_body(
    const float* E, const float* __restrict__ Wg, float acc[OT][4],
    int c0, int pr, int px, int og_base, int C_total)
{
#pragma unroll 1
    for (int cc = 0; cc < CT; cc++) {
        int c = c0 + cc;
#pragma unroll
        for (int g = 0; g < 7; g++) {
            float e[4][4];
            const int base = ((c * Yd + 2 * pr) * 7 + g) * Xd + 2 * px;
#pragma unroll
            for (int dy = 0; dy < 4; dy++) {
                const float2* r = reinterpret_cast<const float2*>(&E[base + dy * 7 * Xd]);
                float2 a = r[0], b2 = r[1];
                e[dy][0] = a.x; e[dy][1] = a.y; e[dy][2] = b2.x; e[dy][3] = b2.y;
            }
#pragma unroll
            for (int o = 0; o < OT; o++) {
                const float4* wv = reinterpret_cast<const float4*>(
                    &Wg[(((og_base + o * C_total) + c) * 7 + g) * 12]);
                float4 w0 = __ldg(&wv[0]);
                float4 w1 = __ldg(&wv[1]);
                float4 w2 = __ldg(&wv[2]);
                float wk[9] = {w0.x, w0.y, w0.z, w0.w, w1.x, w1.y, w1.z, w1.w, w2.x};
#pragma unroll
                for (int kh = 0; kh < 3; kh++)
#pragma unroll
                    for (int kw = 0; kw < 3; kw++) {
                        float wgt = wk[kh * 3 + kw];
                        acc[o][0] += e[kh][kw] * wgt;
                        acc[o][1] += e[kh][kw + 1] * wgt;
                        acc[o][2] += e[kh + 1][kw] * wgt;
                        acc[o][3] += e[kh + 1][kw + 1] * wgt;
                    }
            }
        }
    }
}

// ---------------- phi expansion of a strip into smem ----------------
template <int C, int H, int W, int SR, int THREADS>
__device__ __forceinline__ void expand_strip(
    const float* __restrict__ inb, float* E, int s, int tid)
{
    constexpr int Yd = 2 * SR + 2, Xd = W + 2;
    const int gy0 = 2 * s * SR - 1;
    for (int i = tid; i < C * Yd * Xd; i += THREADS) {
        int x  = i % Xd;
        int ly = (i / Xd) % Yd;
        int c  = i / (Xd * Yd);
        int gy = gy0 + ly;
        float v = 0.0f;
        if (gy >= 0 && gy < H && x >= 1 && x <= W) v = __ldg(&inb[(c * H + gy) * W + x - 1]);
        float phi[7];
        compute_phi(v, phi);
#pragma unroll
        for (int g = 0; g < 7; g++) E[((c * Yd + ly) * 7 + g) * Xd + x] = phi[g];
    }
}

// ---------------- layers 1/2: strip kernel, 64 threads, NITER strips/block ----------------
template <int C, int H, int W, int O, int OT, int SR, int NITER>
__global__ void __launch_bounds__(64, 8) kan_layer(
    const float* __restrict__ in, float* __restrict__ out, const float* __restrict__ Wg)
{
    constexpr int PW = W / 2, PH = H / 2;
    constexpr int OG = O / OT;
    constexpr int STRIPS_G = PH / SR / NITER;  // strips per grid index
    constexpr int Yd = 2 * SR + 2, Xd = W + 2;
    constexpr int THREADS = PW * SR * OG;
    static_assert(THREADS == 64, "block must be 64 threads");

    extern __shared__ float E[];

    const int b   = blockIdx.x / STRIPS_G;
    const int s0  = blockIdx.x % STRIPS_G;
    const int tid = threadIdx.x;

    const int px = tid % PW;
    const int pr = (tid / PW) % SR;
    const int og = tid / (PW * SR);

#pragma unroll
    for (int it = 0; it < NITER; it++) {
        const int s = s0 + it * STRIPS_G;

        expand_strip<C, H, W, SR, THREADS>(in + (size_t)b * C * H * W, E, s, tid);
        __syncthreads();

        float acc[OT][4];
#pragma unroll
        for (int o = 0; o < OT; o++) acc[o][0] = acc[o][1] = acc[o][2] = acc[o][3] = 0.0f;

        conv_body<C, OT, Yd, Xd>(E, Wg, acc, 0, pr, px, og * OT * C, C);

        float* outb = out + (size_t)b * O * PH * PW;
        const int prow = s * SR + pr;
#pragma unroll
        for (int o = 0; o < OT; o++) {
            float m = fmaxf(fmaxf(acc[o][0], acc[o][1]), fmaxf(acc[o][2], acc[o][3]));
            outb[((og * OT + o) * PH + prow) * PW + px] = m;
        }
        if (it + 1 < NITER) __syncthreads();   // protect E before next expansion
    }
}

// ---------------- layer 3: channel-split (CS=2), 128 threads ----------------
__global__ void __launch_bounds__(128, 4) kan_layer3(
    const float* __restrict__ in, float* __restrict__ out, const float* __restrict__ Wg)
{
    constexpr int C = 16, H = 8, W = 8, O = 32, OT = 4, SR = 2;
    constexpr int PW = W / 2, PH = H / 2;
    constexpr int OG = O / OT;                 // 8
    constexpr int STRIPS = PH / SR;            // 2
    constexpr int Yd = 2 * SR + 2, Xd = W + 2; // 6, 10
    constexpr int THREADS = 128;
    constexpr int HALF = 64;

    extern __shared__ float E[];               // 16*6*7*10 = 6720 floats

    const int b   = blockIdx.x / STRIPS;
    const int s   = blockIdx.x % STRIPS;
    const int tid = threadIdx.x;

    expand_strip<C, H, W, SR, THREADS>(in + (size_t)b * C * H * W, E, s, tid);
    __syncthreads();

    const int px = tid % PW;
    const int pr = (tid / PW) % SR;
    const int og = (tid / (PW * SR)) % OG;
    const int cs = tid / (PW * SR * OG);

    float acc[OT][4];
#pragma unroll
    for (int o = 0; o < OT; o++) acc[o][0] = acc[o][1] = acc[o][2] = acc[o][3] = 0.0f;

    conv_body<8, OT, Yd, Xd>(E, Wg, acc, cs * 8, pr, px, og * OT * C, C);

    __syncthreads();                            // all conv reads of E done
    float* P = E;                               // reuse arena: 64*17 floats
    const int slot = tid % HALF;                // same (px,pr,og) across halves
    if (cs == 1) {
#pragma unroll
        for (int o = 0; o < OT; o++)
#pragma unroll
            for (int k = 0; k < 4; k++) P[slot * 17 + o * 4 + k] = acc[o][k];
    }
    __syncthreads();
    if (cs == 0) {
        float* outb = out + (size_t)b * O * PH * PW;
        const int prow = s * SR + pr;
#pragma unroll
        for (int o = 0; o < OT; o++) {
            float v0 = acc[o][0] + P[slot * 17 + o * 4 + 0];
            float v1 = acc[o][1] + P[slot * 17 + o * 4 + 1];
            float v2 = acc[o][2] + P[slot * 17 + o * 4 + 2];
            float v3 = acc[o][3] + P[slot * 17 + o * 4 + 3];
            float m = fmaxf(fmaxf(v0, v1), fmaxf(v2, v3));
            outb[((og * OT + o) * PH + prow) * PW + px] = m;
        }
    }
}

// ---------------- final linear 512 -> 100 (direct linw rows, float4) ----------------
__global__ void __launch_bounds__(128) linear_k(const float* __restrict__ linw,
                                                const float* __restrict__ bias,
                                                float* __restrict__ out) {
    __shared__ float hs[512];
    int b = blockIdx.x;
    for (int i = threadIdx.x; i < 512; i += 128) hs[i] = g_out3[(size_t)b * 512 + i];
    __syncthreads();
    int j = threadIdx.x;
    if (j < 100) {
        float a = __ldg(&bias[j]);
        const float4* wr = reinterpret_cast<const float4*>(linw + (size_t)j * 512);
        const float4* h4 = reinterpret_cast<const float4*>(hs);
#pragma unroll 8
        for (int f = 0; f < 128; f++) {
            float4 w = __ldg(&wr[f]);
            float4 hv = h4[f];
            a += w.x * hv.x + w.y * hv.y + w.z * hv.z + w.w * hv.w;
        }
        out[(size_t)b * 100 + j] = a;
    }
}

extern "C" void kernel_launch(void* const* d_in, const int* in_sizes, int n_in,
                              void* d_out, int out_size) {
    const float* x     = (const float*)d_in[0];
    const float* c1bw  = (const float*)d_in[1];
    const float* c1sw  = (const float*)d_in[2];
    const float* c1sc  = (const float*)d_in[3];
    const float* c2bw  = (const float*)d_in[4];
    const float* c2sw  = (const float*)d_in[5];
    const float* c2sc  = (const float*)d_in[6];
    const float* c3bw  = (const float*)d_in[7];
    const float* c3sw  = (const float*)d_in[8];
    const float* c3sc  = (const float*)d_in[9];
    const float* linw  = (const float*)d_in[10];
    const float* linb  = (const float*)d_in[11];
    float* out = (float*)d_out;

    static float *p_W1, *p_W2, *p_W3, *p_o1, *p_o2, *p_o3;
    static bool init = false;
    if (!init) {
        cudaGetSymbolAddress((void**)&p_W1, g_W1);
        cudaGetSymbolAddress((void**)&p_W2, g_W2);
        cudaGetSymbolAddress((void**)&p_W3, g_W3);
        cudaGetSymbolAddress((void**)&p_o1, g_out1);
        cudaGetSymbolAddress((void**)&p_o2, g_out2);
        cudaGetSymbolAddress((void**)&p_o3, g_out3);
        init = true;
    }

    prep_all<<<(NPREP + 255) / 256, 256>>>(c1bw, c1sw, c1sc, c2bw, c2sw, c2sc,
                                           c3bw, c3sw, c3sc);

    // L1: C=3 O=8  OT=4 SR=2 NITER=2 -> 64 thr, 4 grid-strips (2 each), grid 1024
    //     single wave at 8 blocks/SM (1024 < 1184). smem 17136 B
    kan_layer<3, 32, 32, 8, 4, 2, 2><<<BATCH * 4, 64, 3 * 6 * 7 * 34 * 4>>>(x, p_o1, p_W1);
    // L2: C=8 O=16 OT=4 SR=2 NITER=1 -> 64 thr, 4 strips, grid 1024, smem 24192 B
    kan_layer<8, 16, 16, 16, 4, 2, 1><<<BATCH * 4, 64, 8 * 6 * 7 * 18 * 4>>>(p_o1, p_o2, p_W2);
    // L3: C=16 O=32 OT=4 SR=2 CS=2 -> 128 thr, 2 strips, grid 512, smem 26880 B
    kan_layer3<<<BATCH * 2, 128, 16 * 6 * 7 * 10 * 4>>>(p_o2, p_o3, p_W3);

    linear_k<<<BATCH, 128>>>(linw, linb, out);
}